// round 9
// baseline (speedup 1.0000x reference)
#include <cuda_runtime.h>
#include <cuda_fp16.h>
#include <cstdint>

typedef __half h16;

// ---------------- problem constants ----------------
#define NB    8
#define SQ    1024
#define SKV   1024
#define EDIM  1024
#define VOC   32000
#define NL    6
#define MTOT  (NB * SQ)        // 8192
#define SCALE_Q 0.125f

// ---------------- device scratch ----------------
// hi-only activations
__device__ __align__(16) h16  g_x  [MTOT * EDIM];
__device__ __align__(16) h16  g_T  [MTOT * EDIM];
__device__ __align__(16) h16  g_q  [MTOT * EDIM];
__device__ __align__(16) h16  g_p  [NB * SQ * SKV];
__device__ __align__(16) h16  g_o  [MTOT * EDIM];
__device__ __align__(16) h16  g_k  [MTOT * EDIM];
__device__ __align__(16) h16  g_vT [MTOT * EDIM];
__device__ __align__(16) h16  g_lin[VOC * EDIM];
// hi+lo weights (projections)
__device__ __align__(16) h16  g_w_h [3 * EDIM * EDIM];
__device__ __align__(16) h16  g_w_l [3 * EDIM * EDIM];
__device__ __align__(16) h16  g_wo_h[EDIM * EDIM];
__device__ __align__(16) h16  g_wo_l[EDIM * EDIM];
__device__ float g_scores[NB * SQ * SKV];

// ---------------- helpers ----------------
__device__ __forceinline__ void split2h(float v, h16& h, h16& l) {
    h = __float2half_rn(v);
    l = __float2half_rn(v - __half2float(h));
}
__device__ __forceinline__ uint32_t pack2(h16 a, h16 b) {
    __half2 p = __halves2half2(a, b);
    return *reinterpret_cast<uint32_t*>(&p);
}

// fp32 -> fp16 hi+lo, vectorized (n4 = count of float4)
__global__ void split_h(const float* __restrict__ src, h16* __restrict__ h,
                        h16* __restrict__ l, size_t n4) {
    size_t stride = (size_t)gridDim.x * blockDim.x;
    for (size_t i = (size_t)blockIdx.x * blockDim.x + threadIdx.x; i < n4; i += stride) {
        float4 v = reinterpret_cast<const float4*>(src)[i];
        h16 h0, l0, h1, l1, h2, l2, h3, l3;
        split2h(v.x, h0, l0); split2h(v.y, h1, l1);
        split2h(v.z, h2, l2); split2h(v.w, h3, l3);
        reinterpret_cast<uint2*>(h)[i] = make_uint2(pack2(h0, h1), pack2(h2, h3));
        reinterpret_cast<uint2*>(l)[i] = make_uint2(pack2(l0, l1), pack2(l2, l3));
    }
}

// fp32 -> fp16 hi only, vectorized
__global__ void conv_h(const float* __restrict__ src, h16* __restrict__ h, size_t n4) {
    size_t stride = (size_t)gridDim.x * blockDim.x;
    for (size_t i = (size_t)blockIdx.x * blockDim.x + threadIdx.x; i < n4; i += stride) {
        float4 v = reinterpret_cast<const float4*>(src)[i];
        reinterpret_cast<uint2*>(h)[i] =
            make_uint2(pack2(__float2half_rn(v.x), __float2half_rn(v.y)),
                       pack2(__float2half_rn(v.z), __float2half_rn(v.w)));
    }
}

// embedding gather -> fp16 hi; one block (256 thr) per row, 4 cols/thread
__global__ void gather_h(const int* __restrict__ idx, const float* __restrict__ embed,
                         h16* __restrict__ x) {
    int row = blockIdx.x;
    int tok = idx[row];
    const float4* src = reinterpret_cast<const float4*>(embed + (size_t)tok * EDIM);
    float4 v = src[threadIdx.x];
    reinterpret_cast<uint2*>(x + (size_t)row * EDIM)[threadIdx.x] =
        make_uint2(pack2(__float2half_rn(v.x), __float2half_rn(v.y)),
                   pack2(__float2half_rn(v.z), __float2half_rn(v.w)));
}

// row softmax over 1024 cols -> fp16; 256 threads/row
__global__ void softmax_h(const float* __restrict__ S, h16* __restrict__ P) {
    int row = blockIdx.x;
    int t = threadIdx.x;
    int lane = t & 31, w = t >> 5;
    float4 v = reinterpret_cast<const float4*>(S + (size_t)row * SKV)[t];

    float m = fmaxf(fmaxf(v.x, v.y), fmaxf(v.z, v.w));
#pragma unroll
    for (int off = 16; off > 0; off >>= 1)
        m = fmaxf(m, __shfl_xor_sync(0xFFFFFFFFu, m, off));
    __shared__ float red[8];
    if (lane == 0) red[w] = m;
    __syncthreads();
    float mx = red[0];
#pragma unroll
    for (int i = 1; i < 8; i++) mx = fmaxf(mx, red[i]);

    v.x = __expf(v.x - mx); v.y = __expf(v.y - mx);
    v.z = __expf(v.z - mx); v.w = __expf(v.w - mx);
    float s = v.x + v.y + v.z + v.w;
#pragma unroll
    for (int off = 16; off > 0; off >>= 1)
        s += __shfl_xor_sync(0xFFFFFFFFu, s, off);
    __shared__ float red2[8];
    if (lane == 0) red2[w] = s;
    __syncthreads();
    float tot = red2[0];
#pragma unroll
    for (int i = 1; i < 8; i++) tot += red2[i];
    float inv = 1.f / tot;

    reinterpret_cast<uint2*>(P + (size_t)row * SKV)[t] =
        make_uint2(pack2(__float2half_rn(v.x * inv), __float2half_rn(v.y * inv)),
                   pack2(__float2half_rn(v.z * inv), __float2half_rn(v.w * inv)));
}

// ---------------- mma.sync fp16 GEMM, 256x128x32 tile ----------------
// C[m,n] = alpha * sum_k A[m,k]*(Bh[n,k] [+ Bl[n,k]]) + bias[n]
// TWOB: B has hi+lo (2 MMA terms); else single term.
// 256 threads = 8 warps (4m x 2n), warp tile 64x64, 4-stage cp.async.

#define BK        32
#define BM        256
#define BN        128
#define LDROW     80
#define A_BYTES   (BM * LDROW)                // 20480
#define B_BYTES   (BN * LDROW)                // 10240
#define NSTAGE    4
#define GSMEM     (NSTAGE * (A_BYTES + 2 * B_BYTES))  // 163840 (max case)
#define GROUP_Y   8

__device__ __forceinline__ uint32_t smem_u32(const void* p) {
    uint32_t a;
    asm("{ .reg .u64 t; cvta.to.shared.u64 t, %1; cvt.u32.u64 %0, t; }" : "=r"(a) : "l"(p));
    return a;
}

__device__ __forceinline__ void ldm_x4(uint32_t& r0, uint32_t& r1, uint32_t& r2,
                                       uint32_t& r3, uint32_t addr) {
    asm volatile("ldmatrix.sync.aligned.m8n8.x4.shared.b16 {%0,%1,%2,%3}, [%4];"
                 : "=r"(r0), "=r"(r1), "=r"(r2), "=r"(r3) : "r"(addr));
}

__device__ __forceinline__ void mma16816(float* c, const uint32_t* a, const uint32_t* b) {
    asm volatile(
        "mma.sync.aligned.m16n8k16.row.col.f32.f16.f16.f32 "
        "{%0,%1,%2,%3}, {%4,%5,%6,%7}, {%8,%9}, {%0,%1,%2,%3};"
        : "+f"(c[0]), "+f"(c[1]), "+f"(c[2]), "+f"(c[3])
        : "r"(a[0]), "r"(a[1]), "r"(a[2]), "r"(a[3]), "r"(b[0]), "r"(b[1]));
}

template <bool TWOB>
__device__ __forceinline__ void fill_stage(uint32_t sbase,
    const h16* __restrict__ A0, const h16* __restrict__ B0, const h16* __restrict__ B1,
    int K, int k0, int tid)
{
#pragma unroll
    for (int j = 0; j < 4; j++) {
        int e = tid + j * 256;
        int row = e >> 2, c = e & 3;
        uint32_t dst = sbase + row * LDROW + c * 16;
        uint64_t src = __cvta_generic_to_global((const void*)(A0 + (size_t)row * K + k0 + c * 8));
        asm volatile("cp.async.cg.shared.global [%0], [%1], 16;" :: "r"(dst), "l"(src));
    }
#pragma unroll
    for (int j = 0; j < 2; j++) {
        int e = tid + j * 256;
        int row = e >> 2, c = e & 3;
        uint32_t dst = sbase + A_BYTES + row * LDROW + c * 16;
        uint64_t sh = __cvta_generic_to_global((const void*)(B0 + (size_t)row * K + k0 + c * 8));
        asm volatile("cp.async.cg.shared.global [%0], [%1], 16;" :: "r"(dst), "l"(sh));
        if (TWOB) {
            uint64_t sl = __cvta_generic_to_global((const void*)(B1 + (size_t)row * K + k0 + c * 8));
            asm volatile("cp.async.cg.shared.global [%0], [%1], 16;" :: "r"(dst + B_BYTES), "l"(sl));
        }
    }
    asm volatile("cp.async.commit_group;" ::: "memory");
}

template <bool TRANS, bool TWOB>
__global__ void __launch_bounds__(256, 1)
gemm_mma(const h16* __restrict__ A, size_t sA,
         const h16* __restrict__ Bh, const h16* __restrict__ Bl, size_t sB,
         float* __restrict__ Cf, h16* __restrict__ Ch, h16* __restrict__ Cl, size_t sC,
         int M, int N, int K, int ldc, float alpha, const float* __restrict__ bias)
{
    extern __shared__ __align__(128) char smem[];
    const uint32_t sb = smem_u32(smem);
    const int tid  = threadIdx.x;
    const int wid  = tid >> 5;
    const int lane = tid & 31;
    const int wm = wid >> 1;                  // 0..3
    const int wn = wid & 1;                   // 0..1
    const int z  = blockIdx.z;
    constexpr uint32_t STAGE_B = A_BYTES + (TWOB ? 2 : 1) * B_BYTES;

    // grouped rasterization
    int lin = blockIdx.y * gridDim.x + blockIdx.x;
    int gsz = GROUP_Y * gridDim.x;
    int grp = lin / gsz, rem = lin % gsz;
    int span = min(GROUP_Y, (int)gridDim.y - grp * GROUP_Y);
    int by = grp * GROUP_Y + rem % span;
    int bx = rem / span;
    const int m0 = by * BM;
    const int n0 = bx * BN;

    const h16* A0 = A  + (size_t)z * sA + (size_t)m0 * K;
    const h16* B0 = Bh + (size_t)z * sB + (size_t)n0 * K;
    const h16* B1 = TWOB ? (Bl + (size_t)z * sB + (size_t)n0 * K) : nullptr;

    const uint32_t a_base = (uint32_t)((wm * 64 + (lane & 15)) * LDROW + (lane >> 4) * 16);
    const uint32_t b_base = (uint32_t)((wn * 64 + (lane >> 4) * 8 + (lane & 7)) * LDROW
                                       + ((lane >> 3) & 1) * 16);

    float acc[4][8][4];
#pragma unroll
    for (int i = 0; i < 4; i++)
#pragma unroll
        for (int j = 0; j < 8; j++)
#pragma unroll
            for (int r = 0; r < 4; r++) acc[i][j][r] = 0.f;

    const int KT = K / BK;

    fill_stage<TWOB>(sb + 0 * STAGE_B, A0, B0, B1, K, 0, tid);
    fill_stage<TWOB>(sb + 1 * STAGE_B, A0, B0, B1, K, BK, tid);
    fill_stage<TWOB>(sb + 2 * STAGE_B, A0, B0, B1, K, 2 * BK, tid);

    int stage = 0;
    for (int kt = 0; kt < KT; kt++) {
        asm volatile("cp.async.wait_group 2;" ::: "memory");
        __syncthreads();

        int f = kt + 3;
        if (f < KT)
            fill_stage<TWOB>(sb + (f % NSTAGE) * STAGE_B, A0, B0, B1, K, f * BK, tid);

        const uint32_t sA_ = sb + stage * STAGE_B;
        const uint32_t sBh = sA_ + A_BYTES;
        const uint32_t sBl = sBh + B_BYTES;

#pragma unroll
        for (int ks = 0; ks < 2; ks++) {
            const uint32_t ko = ks * 32;
            uint32_t ah[4][4], bh[8][2], bl[8][2];
#pragma unroll
            for (int mi = 0; mi < 4; mi++) {
                uint32_t off = a_base + mi * 16 * LDROW + ko;
                ldm_x4(ah[mi][0], ah[mi][1], ah[mi][2], ah[mi][3], sA_ + off);
            }
#pragma unroll
            for (int p = 0; p < 4; p++) {
                uint32_t off = b_base + p * 16 * LDROW + ko;
                ldm_x4(bh[2 * p][0], bh[2 * p][1], bh[2 * p + 1][0], bh[2 * p + 1][1], sBh + off);
                if (TWOB)
                    ldm_x4(bl[2 * p][0], bl[2 * p][1], bl[2 * p + 1][0], bl[2 * p + 1][1], sBl + off);
            }
#pragma unroll
            for (int mi = 0; mi < 4; mi++)
#pragma unroll
                for (int ni = 0; ni < 8; ni++) {
                    mma16816(acc[mi][ni], ah[mi], bh[ni]);
                    if (TWOB) mma16816(acc[mi][ni], ah[mi], bl[ni]);
                }
        }
        stage = (stage + 1 == NSTAGE) ? 0 : stage + 1;
    }

    asm volatile("cp.async.wait_group 0;" ::: "memory");
    __syncthreads();

    // ---------------- epilogue ----------------
    const int LD = TRANS ? 260 : 132;
    float* SE = reinterpret_cast<float*>(smem);
    const int tr = lane >> 2;
    const int tc = (lane & 3) * 2;
#pragma unroll
    for (int mi = 0; mi < 4; mi++)
#pragma unroll
        for (int ni = 0; ni < 8; ni++) {
            int r0 = wm * 64 + mi * 16 + tr;
            int c0 = wn * 64 + ni * 8 + tc;
            if (!TRANS) {
                SE[r0 * LD + c0]           = acc[mi][ni][0];
                SE[r0 * LD + c0 + 1]       = acc[mi][ni][1];
                SE[(r0 + 8) * LD + c0]     = acc[mi][ni][2];
                SE[(r0 + 8) * LD + c0 + 1] = acc[mi][ni][3];
            } else {
                SE[c0 * LD + r0]           = acc[mi][ni][0];
                SE[(c0 + 1) * LD + r0]     = acc[mi][ni][1];
                SE[c0 * LD + r0 + 8]       = acc[mi][ni][2];
                SE[(c0 + 1) * LD + r0 + 8] = acc[mi][ni][3];
            }
        }
    __syncthreads();

    const int INNER4 = TRANS ? 64 : 32;
    const int OB = TRANS ? n0 : m0;
    const int IB = TRANS ? m0 : n0;
#pragma unroll
    for (int i = 0; i < 32; i++) {
        int e = tid + i * 256;
        int row = e / INNER4;
        int c4 = (e % INNER4) * 4;
        float4 v = *reinterpret_cast<float4*>(&SE[row * LD + c4]);
        v.x *= alpha; v.y *= alpha; v.z *= alpha; v.w *= alpha;
        if (!TRANS && bias) {
            v.x += bias[n0 + c4];
            v.y += bias[n0 + c4 + 1];
            v.z += bias[n0 + c4 + 2];
            v.w += bias[n0 + c4 + 3];
        }
        size_t o = (size_t)z * sC + (size_t)(OB + row) * ldc + IB + c4;
        if (Cf) *reinterpret_cast<float4*>(Cf + o) = v;
        if (Ch) {
            if (Cl) {
                h16 h0, l0, h1, l1, h2, l2, h3, l3;
                split2h(v.x, h0, l0); split2h(v.y, h1, l1);
                split2h(v.z, h2, l2); split2h(v.w, h3, l3);
                *reinterpret_cast<uint2*>(Ch + o) = make_uint2(pack2(h0, h1), pack2(h2, h3));
                *reinterpret_cast<uint2*>(Cl + o) = make_uint2(pack2(l0, l1), pack2(l2, l3));
            } else {
                *reinterpret_cast<uint2*>(Ch + o) =
                    make_uint2(pack2(__float2half_rn(v.x), __float2half_rn(v.y)),
                               pack2(__float2half_rn(v.z), __float2half_rn(v.w)));
            }
        }
    }
}

// ---------------- host-side launcher ----------------
static void launch_gemm(bool trans, bool twob,
                        const h16* A, size_t sA,
                        const h16* Bh, const h16* Bl, size_t sB,
                        float* Cf, h16* Ch, h16* Cl, size_t sC,
                        int M, int N, int K, int ldc, float alpha,
                        const float* bias, int batch) {
    dim3 grid(N / BN, M / BM, batch);
    if (trans)
        gemm_mma<true, true><<<grid, 256, GSMEM>>>(A, sA, Bh, Bl, sB, Cf, Ch, Cl, sC,
                                                   M, N, K, ldc, alpha, bias);
    else if (twob)
        gemm_mma<false, true><<<grid, 256, GSMEM>>>(A, sA, Bh, Bl, sB, Cf, Ch, Cl, sC,
                                                    M, N, K, ldc, alpha, bias);
    else
        gemm_mma<false, false><<<grid, 256, GSMEM>>>(A, sA, Bh, nullptr, sB, Cf, Ch, Cl, sC,
                                                     M, N, K, ldc, alpha, bias);
}

#define SYM(var, sym)                                   \
    do {                                                \
        void* _p = nullptr;                             \
        cudaGetSymbolAddress(&_p, sym);                 \
        var = (decltype(var))_p;                        \
    } while (0)

extern "C" void kernel_launch(void* const* d_in, const int* in_sizes, int n_in,
                              void* d_out, int out_size) {
    const int*   input_text = (const int*)d_in[0];
    const float* target     = (const float*)d_in[1];
    const float* embed      = (const float*)d_in[2];
    const float* in_proj_w  = (const float*)d_in[3];
    const float* out_w      = (const float*)d_in[4];
    const float* out_b      = (const float*)d_in[5];
    const float* lin_w      = (const float*)d_in[6];
    const float* lin_b      = (const float*)d_in[7];
    float*       logits     = (float*)d_out;

    cudaFuncSetAttribute((const void*)gemm_mma<false, true>,
                         cudaFuncAttributeMaxDynamicSharedMemorySize, GSMEM);
    cudaFuncSetAttribute((const void*)gemm_mma<false, false>,
                         cudaFuncAttributeMaxDynamicSharedMemorySize, GSMEM);
    cudaFuncSetAttribute((const void*)gemm_mma<true, true>,
                         cudaFuncAttributeMaxDynamicSharedMemorySize, GSMEM);

    h16 *x, *T, *q, *p, *o, *k, *vT, *lin;
    h16 *w_h, *w_l, *wo_h, *wo_l;
    float* sc;
    SYM(x, g_x);   SYM(T, g_T);   SYM(q, g_q);   SYM(p, g_p);   SYM(o, g_o);
    SYM(k, g_k);   SYM(vT, g_vT); SYM(lin, g_lin);
    SYM(w_h, g_w_h);   SYM(w_l, g_w_l);
    SYM(wo_h, g_wo_h); SYM(wo_l, g_wo_l);
    SYM(sc, g_scores);

    gather_h<<<MTOT, 256>>>(input_text, embed, x);          // launch 1
    conv_h<<<4096, 256>>>(target, T, (size_t)MTOT * EDIM / 4);  // launch 2

    const size_t EE = (size_t)EDIM * EDIM;

    for (int l = 0; l < NL; l++) {
        split_h<<<3072, 256>>>(in_proj_w + (size_t)l * 3 * EE, w_h, w_l, 3 * EE / 4);  // 3

        // q = (x @ Wq^T) * SCALE      (hi only out)   <- 4th launch: profiled GEMM
        launch_gemm(false, true, x, 0, w_h, w_l, 0,
                    nullptr, q, nullptr, 0,
                    MTOT, EDIM, EDIM, EDIM, SCALE_Q, nullptr, 1);

        split_h<<<1024, 256>>>(out_w + (size_t)l * EE, wo_h, wo_l, EE / 4);

        // k = target @ Wk^T           (hi only out)
        launch_gemm(false, true, T, 0, w_h + EE, w_l + EE, 0,
                    nullptr, k, nullptr, 0,
                    MTOT, EDIM, EDIM, EDIM, 1.f, nullptr, 1);
        // vT[b] = (target_b @ Wv^T)^T (hi only out, transposed store)
        launch_gemm(true, true, T, (size_t)SKV * EDIM, w_h + 2 * EE, w_l + 2 * EE, 0,
                    nullptr, vT, nullptr, (size_t)EDIM * SKV,
                    SKV, EDIM, EDIM, SKV, 1.f, nullptr, NB);
        // scores[b] = q_b @ k_b^T     (fp32 out, single-term B)
        launch_gemm(false, false, q, (size_t)SQ * EDIM, k, nullptr, (size_t)SKV * EDIM,
                    sc, nullptr, nullptr, (size_t)SQ * SKV,
                    SQ, SKV, EDIM, SKV, 1.f, nullptr, NB);
        softmax_h<<<NB * SQ, 256>>>(sc, p);
        // o[b] = attn_b @ vT_b^T      (hi only out, single-term B)
        launch_gemm(false, false, p, (size_t)SQ * SKV, vT, nullptr, (size_t)EDIM * SKV,
                    nullptr, o, nullptr, (size_t)SQ * EDIM,
                    SQ, EDIM, SKV, EDIM, 1.f, nullptr, NB);
        // x = o @ out_w^T + out_b     (hi only out)
        launch_gemm(false, true, o, 0, wo_h, wo_l, 0,
                    nullptr, x, nullptr, 0,
                    MTOT, EDIM, EDIM, EDIM, 1.f, out_b + (size_t)l * EDIM, 1);
    }

    // logits = x @ lin_w^T + lin_b    (fp32 out, single-term B)
    conv_h<<<8192, 256>>>(lin_w, lin, (size_t)VOC * EDIM / 4);
    launch_gemm(false, false, x, 0, lin, nullptr, 0,
                logits, nullptr, nullptr, 0,
                MTOT, VOC, EDIM, VOC, 1.f, lin_b, 1);
}

// round 10
// speedup vs baseline: 1.6410x; 1.6410x over previous
#include <cuda_runtime.h>
#include <cuda_fp16.h>
#include <cstdint>

typedef __half h16;

// ---------------- problem constants ----------------
#define NB    8
#define SQ    1024
#define SKV   1024
#define EDIM  1024
#define VOC   32000
#define NL    6
#define MTOT  (NB * SQ)        // 8192
#define SCALE_Q 0.125f

// ---------------- device scratch ----------------
__device__ __align__(16) h16  g_x  [MTOT * EDIM];
__device__ __align__(16) h16  g_T  [MTOT * EDIM];
__device__ __align__(16) h16  g_q  [MTOT * EDIM];
__device__ __align__(16) h16  g_p  [NB * SQ * SKV];
__device__ __align__(16) h16  g_o  [MTOT * EDIM];
__device__ __align__(16) h16  g_k  [MTOT * EDIM];
__device__ __align__(16) h16  g_vT [MTOT * EDIM];
__device__ __align__(16) h16  g_lin[VOC * EDIM];
__device__ __align__(16) h16  g_w_h [3 * EDIM * EDIM];
__device__ __align__(16) h16  g_w_l [3 * EDIM * EDIM];
__device__ __align__(16) h16  g_wo_h[EDIM * EDIM];
__device__ __align__(16) h16  g_wo_l[EDIM * EDIM];
__device__ float g_scores[NB * SQ * SKV];

// ---------------- helpers ----------------
__device__ __forceinline__ void split2h(float v, h16& h, h16& l) {
    h = __float2half_rn(v);
    l = __float2half_rn(v - __half2float(h));
}
__device__ __forceinline__ uint32_t pack2(h16 a, h16 b) {
    __half2 p = __halves2half2(a, b);
    return *reinterpret_cast<uint32_t*>(&p);
}

__global__ void split_h(const float* __restrict__ src, h16* __restrict__ h,
                        h16* __restrict__ l, size_t n4) {
    size_t stride = (size_t)gridDim.x * blockDim.x;
    for (size_t i = (size_t)blockIdx.x * blockDim.x + threadIdx.x; i < n4; i += stride) {
        float4 v = reinterpret_cast<const float4*>(src)[i];
        h16 h0, l0, h1, l1, h2, l2, h3, l3;
        split2h(v.x, h0, l0); split2h(v.y, h1, l1);
        split2h(v.z, h2, l2); split2h(v.w, h3, l3);
        reinterpret_cast<uint2*>(h)[i] = make_uint2(pack2(h0, h1), pack2(h2, h3));
        reinterpret_cast<uint2*>(l)[i] = make_uint2(pack2(l0, l1), pack2(l2, l3));
    }
}

__global__ void conv_h(const float* __restrict__ src, h16* __restrict__ h, size_t n4) {
    size_t stride = (size_t)gridDim.x * blockDim.x;
    for (size_t i = (size_t)blockIdx.x * blockDim.x + threadIdx.x; i < n4; i += stride) {
        float4 v = reinterpret_cast<const float4*>(src)[i];
        reinterpret_cast<uint2*>(h)[i] =
            make_uint2(pack2(__float2half_rn(v.x), __float2half_rn(v.y)),
                       pack2(__float2half_rn(v.z), __float2half_rn(v.w)));
    }
}

__global__ void gather_h(const int* __restrict__ idx, const float* __restrict__ embed,
                         h16* __restrict__ x) {
    int row = blockIdx.x;
    int tok = idx[row];
    const float4* src = reinterpret_cast<const float4*>(embed + (size_t)tok * EDIM);
    float4 v = src[threadIdx.x];
    reinterpret_cast<uint2*>(x + (size_t)row * EDIM)[threadIdx.x] =
        make_uint2(pack2(__float2half_rn(v.x), __float2half_rn(v.y)),
                   pack2(__float2half_rn(v.z), __float2half_rn(v.w)));
}

__global__ void softmax_h(const float* __restrict__ S, h16* __restrict__ P) {
    int row = blockIdx.x;
    int t = threadIdx.x;
    int lane = t & 31, w = t >> 5;
    float4 v = reinterpret_cast<const float4*>(S + (size_t)row * SKV)[t];

    float m = fmaxf(fmaxf(v.x, v.y), fmaxf(v.z, v.w));
#pragma unroll
    for (int off = 16; off > 0; off >>= 1)
        m = fmaxf(m, __shfl_xor_sync(0xFFFFFFFFu, m, off));
    __shared__ float red[8];
    if (lane == 0) red[w] = m;
    __syncthreads();
    float mx = red[0];
#pragma unroll
    for (int i = 1; i < 8; i++) mx = fmaxf(mx, red[i]);

    v.x = __expf(v.x - mx); v.y = __expf(v.y - mx);
    v.z = __expf(v.z - mx); v.w = __expf(v.w - mx);
    float s = v.x + v.y + v.z + v.w;
#pragma unroll
    for (int off = 16; off > 0; off >>= 1)
        s += __shfl_xor_sync(0xFFFFFFFFu, s, off);
    __shared__ float red2[8];
    if (lane == 0) red2[w] = s;
    __syncthreads();
    float tot = red2[0];
#pragma unroll
    for (int i = 1; i < 8; i++) tot += red2[i];
    float inv = 1.f / tot;

    reinterpret_cast<uint2*>(P + (size_t)row * SKV)[t] =
        make_uint2(pack2(__float2half_rn(v.x * inv), __float2half_rn(v.y * inv)),
                   pack2(__float2half_rn(v.z * inv), __float2half_rn(v.w * inv)));
}

// ---------------- mma.sync fp16 GEMM, 256x128x32 tile, 512 threads ----------------
// C[m,n] = alpha * sum_k A[m,k]*(Bh[n,k] [+ Bl[n,k]]) + bias[n]
// 16 warps as 4(m) x 4(n); warp tile 64x32; 4-stage cp.async.

#define BK        32
#define BM        256
#define BN        128
#define NTHR      512
#define LDROW     80
#define A_BYTES   (BM * LDROW)                // 20480
#define B_BYTES   (BN * LDROW)                // 10240
#define NSTAGE    4
#define GSMEM     (NSTAGE * (A_BYTES + 2 * B_BYTES))  // 163840 (max case)
#define GROUP_Y   8

__device__ __forceinline__ uint32_t smem_u32(const void* p) {
    uint32_t a;
    asm("{ .reg .u64 t; cvta.to.shared.u64 t, %1; cvt.u32.u64 %0, t; }" : "=r"(a) : "l"(p));
    return a;
}

__device__ __forceinline__ void ldm_x4(uint32_t& r0, uint32_t& r1, uint32_t& r2,
                                       uint32_t& r3, uint32_t addr) {
    asm volatile("ldmatrix.sync.aligned.m8n8.x4.shared.b16 {%0,%1,%2,%3}, [%4];"
                 : "=r"(r0), "=r"(r1), "=r"(r2), "=r"(r3) : "r"(addr));
}

__device__ __forceinline__ void mma16816(float* c, const uint32_t* a, const uint32_t* b) {
    asm volatile(
        "mma.sync.aligned.m16n8k16.row.col.f32.f16.f16.f32 "
        "{%0,%1,%2,%3}, {%4,%5,%6,%7}, {%8,%9}, {%0,%1,%2,%3};"
        : "+f"(c[0]), "+f"(c[1]), "+f"(c[2]), "+f"(c[3])
        : "r"(a[0]), "r"(a[1]), "r"(a[2]), "r"(a[3]), "r"(b[0]), "r"(b[1]));
}

template <bool TWOB>
__device__ __forceinline__ void fill_stage(uint32_t sbase,
    const h16* __restrict__ A0, const h16* __restrict__ B0, const h16* __restrict__ B1,
    int K, int k0, int tid)
{
    // A: 256 rows x 4 chunks of 16B = 1024 tasks, 512 threads -> 2 rounds
#pragma unroll
    for (int j = 0; j < 2; j++) {
        int e = tid + j * NTHR;
        int row = e >> 2, c = e & 3;
        uint32_t dst = sbase + row * LDROW + c * 16;
        uint64_t src = __cvta_generic_to_global((const void*)(A0 + (size_t)row * K + k0 + c * 8));
        asm volatile("cp.async.cg.shared.global [%0], [%1], 16;" :: "r"(dst), "l"(src));
    }
    // B: 128 rows x 4 chunks = 512 tasks -> 1 round
    {
        int e = tid;
        int row = e >> 2, c = e & 3;
        uint32_t dst = sbase + A_BYTES + row * LDROW + c * 16;
        uint64_t sh = __cvta_generic_to_global((const void*)(B0 + (size_t)row * K + k0 + c * 8));
        asm volatile("cp.async.cg.shared.global [%0], [%1], 16;" :: "r"(dst), "l"(sh));
        if (TWOB) {
            uint64_t sl = __cvta_generic_to_global((const void*)(B1 + (size_t)row * K + k0 + c * 8));
            asm volatile("cp.async.cg.shared.global [%0], [%1], 16;" :: "r"(dst + B_BYTES), "l"(sl));
        }
    }
    asm volatile("cp.async.commit_group;" ::: "memory");
}

template <bool TRANS, bool TWOB>
__global__ void __launch_bounds__(NTHR, 1)
gemm_mma(const h16* __restrict__ A, size_t sA,
         const h16* __restrict__ Bh, const h16* __restrict__ Bl, size_t sB,
         float* __restrict__ Cf, h16* __restrict__ Ch, h16* __restrict__ Cl, size_t sC,
         int M, int N, int K, int ldc, float alpha, const float* __restrict__ bias)
{
    extern __shared__ __align__(128) char smem[];
    const uint32_t sb = smem_u32(smem);
    const int tid  = threadIdx.x;
    const int wid  = tid >> 5;
    const int lane = tid & 31;
    const int wm = wid >> 2;                  // 0..3 : 64-row block
    const int wn = wid & 3;                   // 0..3 : 32-col block
    const int z  = blockIdx.z;
    constexpr uint32_t STAGE_B = A_BYTES + (TWOB ? 2 : 1) * B_BYTES;

    // grouped rasterization
    int lin = blockIdx.y * gridDim.x + blockIdx.x;
    int gsz = GROUP_Y * gridDim.x;
    int grp = lin / gsz, rem = lin % gsz;
    int span = min(GROUP_Y, (int)gridDim.y - grp * GROUP_Y);
    int by = grp * GROUP_Y + rem % span;
    int bx = rem / span;
    const int m0 = by * BM;
    const int n0 = bx * BN;

    const h16* A0 = A  + (size_t)z * sA + (size_t)m0 * K;
    const h16* B0 = Bh + (size_t)z * sB + (size_t)n0 * K;
    const h16* B1 = TWOB ? (Bl + (size_t)z * sB + (size_t)n0 * K) : nullptr;

    const uint32_t a_base = (uint32_t)((wm * 64 + (lane & 15)) * LDROW + (lane >> 4) * 16);
    const uint32_t b_base = (uint32_t)((wn * 32 + (lane >> 4) * 8 + (lane & 7)) * LDROW
                                       + ((lane >> 3) & 1) * 16);

    float acc[4][4][4];
#pragma unroll
    for (int i = 0; i < 4; i++)
#pragma unroll
        for (int j = 0; j < 4; j++)
#pragma unroll
            for (int r = 0; r < 4; r++) acc[i][j][r] = 0.f;

    const int KT = K / BK;

    fill_stage<TWOB>(sb + 0 * STAGE_B, A0, B0, B1, K, 0, tid);
    fill_stage<TWOB>(sb + 1 * STAGE_B, A0, B0, B1, K, BK, tid);
    fill_stage<TWOB>(sb + 2 * STAGE_B, A0, B0, B1, K, 2 * BK, tid);

    int stage = 0;
    for (int kt = 0; kt < KT; kt++) {
        asm volatile("cp.async.wait_group 2;" ::: "memory");
        __syncthreads();

        int f = kt + 3;
        if (f < KT)
            fill_stage<TWOB>(sb + (f % NSTAGE) * STAGE_B, A0, B0, B1, K, f * BK, tid);

        const uint32_t sA_ = sb + stage * STAGE_B;
        const uint32_t sBh = sA_ + A_BYTES;
        const uint32_t sBl = sBh + B_BYTES;

#pragma unroll
        for (int ks = 0; ks < 2; ks++) {
            const uint32_t ko = ks * 32;
            uint32_t ah[4][4], bh[4][2], bl[4][2];
#pragma unroll
            for (int mi = 0; mi < 4; mi++) {
                uint32_t off = a_base + mi * 16 * LDROW + ko;
                ldm_x4(ah[mi][0], ah[mi][1], ah[mi][2], ah[mi][3], sA_ + off);
            }
#pragma unroll
            for (int p = 0; p < 2; p++) {     // each x4 covers two n8 blocks
                uint32_t off = b_base + p * 16 * LDROW + ko;
                ldm_x4(bh[2 * p][0], bh[2 * p][1], bh[2 * p + 1][0], bh[2 * p + 1][1], sBh + off);
                if (TWOB)
                    ldm_x4(bl[2 * p][0], bl[2 * p][1], bl[2 * p + 1][0], bl[2 * p + 1][1], sBl + off);
            }
#pragma unroll
            for (int mi = 0; mi < 4; mi++)
#pragma unroll
                for (int ni = 0; ni < 4; ni++) {
                    mma16816(acc[mi][ni], ah[mi], bh[ni]);
                    if (TWOB) mma16816(acc[mi][ni], ah[mi], bl[ni]);
                }
        }
        stage = (stage + 1 == NSTAGE) ? 0 : stage + 1;
    }

    asm volatile("cp.async.wait_group 0;" ::: "memory");
    __syncthreads();

    // ---------------- epilogue ----------------
    const int LD = TRANS ? 260 : 132;
    float* SE = reinterpret_cast<float*>(smem);
    const int tr = lane >> 2;
    const int tc = (lane & 3) * 2;
#pragma unroll
    for (int mi = 0; mi < 4; mi++)
#pragma unroll
        for (int ni = 0; ni < 4; ni++) {
            int r0 = wm * 64 + mi * 16 + tr;
            int c0 = wn * 32 + ni * 8 + tc;
            if (!TRANS) {
                SE[r0 * LD + c0]           = acc[mi][ni][0];
                SE[r0 * LD + c0 + 1]       = acc[mi][ni][1];
                SE[(r0 + 8) * LD + c0]     = acc[mi][ni][2];
                SE[(r0 + 8) * LD + c0 + 1] = acc[mi][ni][3];
            } else {
                SE[c0 * LD + r0]           = acc[mi][ni][0];
                SE[(c0 + 1) * LD + r0]     = acc[mi][ni][1];
                SE[c0 * LD + r0 + 8]       = acc[mi][ni][2];
                SE[(c0 + 1) * LD + r0 + 8] = acc[mi][ni][3];
            }
        }
    __syncthreads();

    const int INNER4 = TRANS ? 64 : 32;       // float4s per staged row
    const int OB = TRANS ? n0 : m0;
    const int IB = TRANS ? m0 : n0;
#pragma unroll
    for (int i = 0; i < 16; i++) {
        int e = tid + i * NTHR;               // 0..8191 float4s
        int row = e / INNER4;
        int c4 = (e % INNER4) * 4;
        float4 v = *reinterpret_cast<float4*>(&SE[row * LD + c4]);
        v.x *= alpha; v.y *= alpha; v.z *= alpha; v.w *= alpha;
        if (!TRANS && bias) {
            v.x += bias[n0 + c4];
            v.y += bias[n0 + c4 + 1];
            v.z += bias[n0 + c4 + 2];
            v.w += bias[n0 + c4 + 3];
        }
        size_t o = (size_t)z * sC + (size_t)(OB + row) * ldc + IB + c4;
        if (Cf) *reinterpret_cast<float4*>(Cf + o) = v;
        if (Ch) {
            if (Cl) {
                h16 h0, l0, h1, l1, h2, l2, h3, l3;
                split2h(v.x, h0, l0); split2h(v.y, h1, l1);
                split2h(v.z, h2, l2); split2h(v.w, h3, l3);
                *reinterpret_cast<uint2*>(Ch + o) = make_uint2(pack2(h0, h1), pack2(h2, h3));
                *reinterpret_cast<uint2*>(Cl + o) = make_uint2(pack2(l0, l1), pack2(l2, l3));
            } else {
                *reinterpret_cast<uint2*>(Ch + o) =
                    make_uint2(pack2(__float2half_rn(v.x), __float2half_rn(v.y)),
                               pack2(__float2half_rn(v.z), __float2half_rn(v.w)));
            }
        }
    }
}

// ---------------- host-side launcher ----------------
static void launch_gemm(bool trans, bool twob,
                        const h16* A, size_t sA,
                        const h16* Bh, const h16* Bl, size_t sB,
                        float* Cf, h16* Ch, h16* Cl, size_t sC,
                        int M, int N, int K, int ldc, float alpha,
                        const float* bias, int batch) {
    dim3 grid(N / BN, M / BM, batch);
    if (trans)
        gemm_mma<true, true><<<grid, NTHR, GSMEM>>>(A, sA, Bh, Bl, sB, Cf, Ch, Cl, sC,
                                                    M, N, K, ldc, alpha, bias);
    else if (twob)
        gemm_mma<false, true><<<grid, NTHR, GSMEM>>>(A, sA, Bh, Bl, sB, Cf, Ch, Cl, sC,
                                                     M, N, K, ldc, alpha, bias);
    else
        gemm_mma<false, false><<<grid, NTHR, GSMEM>>>(A, sA, Bh, nullptr, sB, Cf, Ch, Cl, sC,
                                                      M, N, K, ldc, alpha, bias);
}

#define SYM(var, sym)                                   \
    do {                                                \
        void* _p = nullptr;                             \
        cudaGetSymbolAddress(&_p, sym);                 \
        var = (decltype(var))_p;                        \
    } while (0)

extern "C" void kernel_launch(void* const* d_in, const int* in_sizes, int n_in,
                              void* d_out, int out_size) {
    const int*   input_text = (const int*)d_in[0];
    const float* target     = (const float*)d_in[1];
    const float* embed      = (const float*)d_in[2];
    const float* in_proj_w  = (const float*)d_in[3];
    const float* out_w      = (const float*)d_in[4];
    const float* out_b      = (const float*)d_in[5];
    const float* lin_w      = (const float*)d_in[6];
    const float* lin_b      = (const float*)d_in[7];
    float*       logits     = (float*)d_out;

    cudaFuncSetAttribute(gemm_mma<false, true>,
                         cudaFuncAttributeMaxDynamicSharedMemorySize, GSMEM);
    cudaFuncSetAttribute(gemm_mma<false, false>,
                         cudaFuncAttributeMaxDynamicSharedMemorySize, GSMEM);
    cudaFuncSetAttribute(gemm_mma<true, true>,
                         cudaFuncAttributeMaxDynamicSharedMemorySize, GSMEM);

    h16 *x, *T, *q, *p, *o, *k, *vT, *lin;
    h16 *w_h, *w_l, *wo_h, *wo_l;
    float* sc;
    SYM(x, g_x);   SYM(T, g_T);   SYM(q, g_q);   SYM(p, g_p);   SYM(o, g_o);
    SYM(k, g_k);   SYM(vT, g_vT); SYM(lin, g_lin);
    SYM(w_h, g_w_h);   SYM(w_l, g_w_l);
    SYM(wo_h, g_wo_h); SYM(wo_l, g_wo_l);
    SYM(sc, g_scores);

    gather_h<<<MTOT, 256>>>(input_text, embed, x);              // launch 1
    conv_h<<<4096, 256>>>(target, T, (size_t)MTOT * EDIM / 4);  // launch 2

    const size_t EE = (size_t)EDIM * EDIM;

    for (int l = 0; l < NL; l++) {
        split_h<<<3072, 256>>>(in_proj_w + (size_t)l * 3 * EE, w_h, w_l, 3 * EE / 4);  // 3

        // q = (x @ Wq^T) * SCALE      (hi only out)   <- 4th launch: profiled GEMM
        launch_gemm(false, true, x, 0, w_h, w_l, 0,
                    nullptr, q, nullptr, 0,
                    MTOT, EDIM, EDIM, EDIM, SCALE_Q, nullptr, 1);

        split_h<<<1024, 256>>>(out_w + (size_t)l * EE, wo_h, wo_l, EE / 4);

        // k = target @ Wk^T           (hi only out)
        launch_gemm(false, true, T, 0, w_h + EE, w_l + EE, 0,
                    nullptr, k, nullptr, 0,
                    MTOT, EDIM, EDIM, EDIM, 1.f, nullptr, 1);
        // vT[b] = (target_b @ Wv^T)^T (hi only out, transposed store)
        launch_gemm(true, true, T, (size_t)SKV * EDIM, w_h + 2 * EE, w_l + 2 * EE, 0,
                    nullptr, vT, nullptr, (size_t)EDIM * SKV,
                    SKV, EDIM, EDIM, SKV, 1.f, nullptr, NB);
        // scores[b] = q_b @ k_b^T     (fp32 out, single-term B)
        launch_gemm(false, false, q, (size_t)SQ * EDIM, k, nullptr, (size_t)SKV * EDIM,
                    sc, nullptr, nullptr, (size_t)SQ * SKV,
                    SQ, SKV, EDIM, SKV, 1.f, nullptr, NB);
        softmax_h<<<NB * SQ, 256>>>(sc, p);
        // o[b] = attn_b @ vT_b^T      (hi only out, single-term B)
        launch_gemm(false, false, p, (size_t)SQ * SKV, vT, nullptr, (size_t)EDIM * SKV,
                    nullptr, o, nullptr, (size_t)SQ * EDIM,
                    SQ, EDIM, SKV, EDIM, 1.f, nullptr, NB);
        // x = o @ out_w^T + out_b     (hi only out)
        launch_gemm(false, true, o, 0, wo_h, wo_l, 0,
                    nullptr, x, nullptr, 0,
                    MTOT, EDIM, EDIM, EDIM, 1.f, out_b + (size_t)l * EDIM, 1);
    }

    // logits = x @ lin_w^T + lin_b    (fp32 out, single-term B)
    conv_h<<<8192, 256>>>(lin_w, lin, (size_t)VOC * EDIM / 4);
    launch_gemm(false, false, x, 0, lin, nullptr, 0,
                logits, nullptr, nullptr, 0,
                MTOT, VOC, EDIM, VOC, 1.f, lin_b, 1);
}

// round 11
// speedup vs baseline: 1.6858x; 1.0273x over previous
#include <cuda_runtime.h>
#include <cuda_fp16.h>
#include <cstdint>

typedef __half h16;

// ---------------- problem constants ----------------
#define NB    8
#define SQ    1024
#define SKV   1024
#define EDIM  1024
#define VOC   32000
#define NL    6
#define MTOT  (NB * SQ)        // 8192
#define SCALE_Q 0.125f

// ---------------- device scratch ----------------
__device__ __align__(16) h16  g_x  [MTOT * EDIM];
__device__ __align__(16) h16  g_T  [MTOT * EDIM];
__device__ __align__(16) h16  g_q  [MTOT * EDIM];
__device__ __align__(16) h16  g_p  [NB * SQ * SKV];
__device__ __align__(16) h16  g_o  [MTOT * EDIM];
__device__ __align__(16) h16  g_k  [MTOT * EDIM];
__device__ __align__(16) h16  g_vT [MTOT * EDIM];
__device__ __align__(16) h16  g_lin[VOC * EDIM];
__device__ __align__(16) h16  g_w_h [3 * EDIM * EDIM];
__device__ __align__(16) h16  g_w_l [3 * EDIM * EDIM];
__device__ __align__(16) h16  g_wo_h[EDIM * EDIM];
__device__ __align__(16) h16  g_wo_l[EDIM * EDIM];
__device__ float g_scores[NB * SQ * SKV];

// ---------------- helpers ----------------
__device__ __forceinline__ void split2h(float v, h16& h, h16& l) {
    h = __float2half_rn(v);
    l = __float2half_rn(v - __half2float(h));
}
__device__ __forceinline__ uint32_t pack2(h16 a, h16 b) {
    __half2 p = __halves2half2(a, b);
    return *reinterpret_cast<uint32_t*>(&p);
}

__global__ void split_h(const float* __restrict__ src, h16* __restrict__ h,
                        h16* __restrict__ l, size_t n4) {
    size_t stride = (size_t)gridDim.x * blockDim.x;
    for (size_t i = (size_t)blockIdx.x * blockDim.x + threadIdx.x; i < n4; i += stride) {
        float4 v = reinterpret_cast<const float4*>(src)[i];
        h16 h0, l0, h1, l1, h2, l2, h3, l3;
        split2h(v.x, h0, l0); split2h(v.y, h1, l1);
        split2h(v.z, h2, l2); split2h(v.w, h3, l3);
        reinterpret_cast<uint2*>(h)[i] = make_uint2(pack2(h0, h1), pack2(h2, h3));
        reinterpret_cast<uint2*>(l)[i] = make_uint2(pack2(l0, l1), pack2(l2, l3));
    }
}

__global__ void conv_h(const float* __restrict__ src, h16* __restrict__ h, size_t n4) {
    size_t stride = (size_t)gridDim.x * blockDim.x;
    for (size_t i = (size_t)blockIdx.x * blockDim.x + threadIdx.x; i < n4; i += stride) {
        float4 v = reinterpret_cast<const float4*>(src)[i];
        reinterpret_cast<uint2*>(h)[i] =
            make_uint2(pack2(__float2half_rn(v.x), __float2half_rn(v.y)),
                       pack2(__float2half_rn(v.z), __float2half_rn(v.w)));
    }
}

__global__ void gather_h(const int* __restrict__ idx, const float* __restrict__ embed,
                         h16* __restrict__ x) {
    int row = blockIdx.x;
    int tok = idx[row];
    const float4* src = reinterpret_cast<const float4*>(embed + (size_t)tok * EDIM);
    float4 v = src[threadIdx.x];
    reinterpret_cast<uint2*>(x + (size_t)row * EDIM)[threadIdx.x] =
        make_uint2(pack2(__float2half_rn(v.x), __float2half_rn(v.y)),
                   pack2(__float2half_rn(v.z), __float2half_rn(v.w)));
}

__global__ void softmax_h(const float* __restrict__ S, h16* __restrict__ P) {
    int row = blockIdx.x;
    int t = threadIdx.x;
    int lane = t & 31, w = t >> 5;
    float4 v = reinterpret_cast<const float4*>(S + (size_t)row * SKV)[t];

    float m = fmaxf(fmaxf(v.x, v.y), fmaxf(v.z, v.w));
#pragma unroll
    for (int off = 16; off > 0; off >>= 1)
        m = fmaxf(m, __shfl_xor_sync(0xFFFFFFFFu, m, off));
    __shared__ float red[8];
    if (lane == 0) red[w] = m;
    __syncthreads();
    float mx = red[0];
#pragma unroll
    for (int i = 1; i < 8; i++) mx = fmaxf(mx, red[i]);

    v.x = __expf(v.x - mx); v.y = __expf(v.y - mx);
    v.z = __expf(v.z - mx); v.w = __expf(v.w - mx);
    float s = v.x + v.y + v.z + v.w;
#pragma unroll
    for (int off = 16; off > 0; off >>= 1)
        s += __shfl_xor_sync(0xFFFFFFFFu, s, off);
    __shared__ float red2[8];
    if (lane == 0) red2[w] = s;
    __syncthreads();
    float tot = red2[0];
#pragma unroll
    for (int i = 1; i < 8; i++) tot += red2[i];
    float inv = 1.f / tot;

    reinterpret_cast<uint2*>(P + (size_t)row * SKV)[t] =
        make_uint2(pack2(__float2half_rn(v.x * inv), __float2half_rn(v.y * inv)),
                   pack2(__float2half_rn(v.z * inv), __float2half_rn(v.w * inv)));
}

// ---------------- mma.sync fp16 GEMM, 128x128x32 tile, 256 threads, 2 CTAs/SM ----------------
// C[m,n] = alpha * sum_k A[m,k]*(Bh[n,k] [+ Bl[n,k]]) + bias[n]
// 8 warps as 2(m) x 4(n); warp tile 64x32. TWOB: 3-stage pipeline; single-B: 4-stage.

#define BK        32
#define BM        128
#define BN        128
#define NTHR      256
#define LDROW     80
#define A_BYTES   (BM * LDROW)                // 10240
#define B_BYTES   (BN * LDROW)                // 10240
#define GROUP_Y   8
// smem budgets (>= epilogue need of 128*132*4 = 67584)
#define SMEM_TWOB   (3 * (A_BYTES + 2 * B_BYTES))   // 92160
#define SMEM_ONEB   (4 * (A_BYTES + B_BYTES))       // 81920

__device__ __forceinline__ uint32_t smem_u32(const void* p) {
    uint32_t a;
    asm("{ .reg .u64 t; cvta.to.shared.u64 t, %1; cvt.u32.u64 %0, t; }" : "=r"(a) : "l"(p));
    return a;
}

__device__ __forceinline__ void ldm_x4(uint32_t& r0, uint32_t& r1, uint32_t& r2,
                                       uint32_t& r3, uint32_t addr) {
    asm volatile("ldmatrix.sync.aligned.m8n8.x4.shared.b16 {%0,%1,%2,%3}, [%4];"
                 : "=r"(r0), "=r"(r1), "=r"(r2), "=r"(r3) : "r"(addr));
}

__device__ __forceinline__ void mma16816(float* c, const uint32_t* a, const uint32_t* b) {
    asm volatile(
        "mma.sync.aligned.m16n8k16.row.col.f32.f16.f16.f32 "
        "{%0,%1,%2,%3}, {%4,%5,%6,%7}, {%8,%9}, {%0,%1,%2,%3};"
        : "+f"(c[0]), "+f"(c[1]), "+f"(c[2]), "+f"(c[3])
        : "r"(a[0]), "r"(a[1]), "r"(a[2]), "r"(a[3]), "r"(b[0]), "r"(b[1]));
}

template <bool TWOB>
__device__ __forceinline__ void fill_stage(uint32_t sbase,
    const h16* __restrict__ A0, const h16* __restrict__ B0, const h16* __restrict__ B1,
    int K, int k0, int tid)
{
    // A: 128 rows x 4 chunks of 16B = 512 tasks, 256 threads -> 2 rounds
#pragma unroll
    for (int j = 0; j < 2; j++) {
        int e = tid + j * NTHR;
        int row = e >> 2, c = e & 3;
        uint32_t dst = sbase + row * LDROW + c * 16;
        uint64_t src = __cvta_generic_to_global((const void*)(A0 + (size_t)row * K + k0 + c * 8));
        asm volatile("cp.async.cg.shared.global [%0], [%1], 16;" :: "r"(dst), "l"(src));
    }
    // B: 128 rows x 4 chunks = 512 tasks -> 2 rounds (hi, + lo if TWOB)
#pragma unroll
    for (int j = 0; j < 2; j++) {
        int e = tid + j * NTHR;
        int row = e >> 2, c = e & 3;
        uint32_t dst = sbase + A_BYTES + row * LDROW + c * 16;
        uint64_t sh = __cvta_generic_to_global((const void*)(B0 + (size_t)row * K + k0 + c * 8));
        asm volatile("cp.async.cg.shared.global [%0], [%1], 16;" :: "r"(dst), "l"(sh));
        if (TWOB) {
            uint64_t sl = __cvta_generic_to_global((const void*)(B1 + (size_t)row * K + k0 + c * 8));
            asm volatile("cp.async.cg.shared.global [%0], [%1], 16;" :: "r"(dst + B_BYTES), "l"(sl));
        }
    }
    asm volatile("cp.async.commit_group;" ::: "memory");
}

template <bool TRANS, bool TWOB>
__global__ void __launch_bounds__(NTHR, 2)
gemm_mma(const h16* __restrict__ A, size_t sA,
         const h16* __restrict__ Bh, const h16* __restrict__ Bl, size_t sB,
         float* __restrict__ Cf, h16* __restrict__ Ch, h16* __restrict__ Cl, size_t sC,
         int M, int N, int K, int ldc, float alpha, const float* __restrict__ bias)
{
    extern __shared__ __align__(128) char smem[];
    const uint32_t sb = smem_u32(smem);
    const int tid  = threadIdx.x;
    const int wid  = tid >> 5;
    const int lane = tid & 31;
    const int wm = wid >> 2;                  // 0..1 : 64-row block
    const int wn = wid & 3;                   // 0..3 : 32-col block
    const int z  = blockIdx.z;
    constexpr int      NSTAGE  = TWOB ? 3 : 4;
    constexpr uint32_t STAGE_B = A_BYTES + (TWOB ? 2 : 1) * B_BYTES;

    // grouped rasterization
    int lin = blockIdx.y * gridDim.x + blockIdx.x;
    int gsz = GROUP_Y * gridDim.x;
    int grp = lin / gsz, rem = lin % gsz;
    int span = min(GROUP_Y, (int)gridDim.y - grp * GROUP_Y);
    int by = grp * GROUP_Y + rem % span;
    int bx = rem / span;
    const int m0 = by * BM;
    const int n0 = bx * BN;

    const h16* A0 = A  + (size_t)z * sA + (size_t)m0 * K;
    const h16* B0 = Bh + (size_t)z * sB + (size_t)n0 * K;
    const h16* B1 = TWOB ? (Bl + (size_t)z * sB + (size_t)n0 * K) : nullptr;

    const uint32_t a_base = (uint32_t)((wm * 64 + (lane & 15)) * LDROW + (lane >> 4) * 16);
    const uint32_t b_base = (uint32_t)((wn * 32 + (lane >> 4) * 8 + (lane & 7)) * LDROW
                                       + ((lane >> 3) & 1) * 16);

    float acc[4][4][4];
#pragma unroll
    for (int i = 0; i < 4; i++)
#pragma unroll
        for (int j = 0; j < 4; j++)
#pragma unroll
            for (int r = 0; r < 4; r++) acc[i][j][r] = 0.f;

    const int KT = K / BK;

#pragma unroll
    for (int s = 0; s < NSTAGE - 1; s++)
        fill_stage<TWOB>(sb + s * STAGE_B, A0, B0, B1, K, s * BK, tid);

    int stage = 0;
    for (int kt = 0; kt < KT; kt++) {
        asm volatile("cp.async.wait_group %0;" :: "n"(NSTAGE - 2) : "memory");
        __syncthreads();

        int f = kt + NSTAGE - 1;
        if (f < KT)
            fill_stage<TWOB>(sb + (f % NSTAGE) * STAGE_B, A0, B0, B1, K, f * BK, tid);
        else
            asm volatile("cp.async.commit_group;" ::: "memory");  // keep group-count semantics

        const uint32_t sA_ = sb + stage * STAGE_B;
        const uint32_t sBh = sA_ + A_BYTES;
        const uint32_t sBl = sBh + B_BYTES;

#pragma unroll
        for (int ks = 0; ks < 2; ks++) {
            const uint32_t ko = ks * 32;
            uint32_t ah[4][4], bh[4][2], bl[4][2];
#pragma unroll
            for (int mi = 0; mi < 4; mi++) {
                uint32_t off = a_base + mi * 16 * LDROW + ko;
                ldm_x4(ah[mi][0], ah[mi][1], ah[mi][2], ah[mi][3], sA_ + off);
            }
#pragma unroll
            for (int p = 0; p < 2; p++) {
                uint32_t off = b_base + p * 16 * LDROW + ko;
                ldm_x4(bh[2 * p][0], bh[2 * p][1], bh[2 * p + 1][0], bh[2 * p + 1][1], sBh + off);
                if (TWOB)
                    ldm_x4(bl[2 * p][0], bl[2 * p][1], bl[2 * p + 1][0], bl[2 * p + 1][1], sBl + off);
            }
#pragma unroll
            for (int mi = 0; mi < 4; mi++)
#pragma unroll
                for (int ni = 0; ni < 4; ni++) {
                    mma16816(acc[mi][ni], ah[mi], bh[ni]);
                    if (TWOB) mma16816(acc[mi][ni], ah[mi], bl[ni]);
                }
        }
        stage = (stage + 1 == NSTAGE) ? 0 : stage + 1;
    }

    asm volatile("cp.async.wait_group 0;" ::: "memory");
    __syncthreads();

    // ---------------- epilogue (128x128, LD=132 both orientations) ----------------
    const int LD = 132;
    float* SE = reinterpret_cast<float*>(smem);
    const int tr = lane >> 2;
    const int tc = (lane & 3) * 2;
#pragma unroll
    for (int mi = 0; mi < 4; mi++)
#pragma unroll
        for (int ni = 0; ni < 4; ni++) {
            int r0 = wm * 64 + mi * 16 + tr;
            int c0 = wn * 32 + ni * 8 + tc;
            if (!TRANS) {
                SE[r0 * LD + c0]           = acc[mi][ni][0];
                SE[r0 * LD + c0 + 1]       = acc[mi][ni][1];
                SE[(r0 + 8) * LD + c0]     = acc[mi][ni][2];
                SE[(r0 + 8) * LD + c0 + 1] = acc[mi][ni][3];
            } else {
                SE[c0 * LD + r0]           = acc[mi][ni][0];
                SE[(c0 + 1) * LD + r0]     = acc[mi][ni][1];
                SE[c0 * LD + r0 + 8]       = acc[mi][ni][2];
                SE[(c0 + 1) * LD + r0 + 8] = acc[mi][ni][3];
            }
        }
    __syncthreads();

    const int OB = TRANS ? n0 : m0;
    const int IB = TRANS ? m0 : n0;
#pragma unroll
    for (int i = 0; i < 16; i++) {
        int e = tid + i * NTHR;               // 0..4095 float4s
        int row = e >> 5;
        int c4 = (e & 31) * 4;
        float4 v = *reinterpret_cast<float4*>(&SE[row * LD + c4]);
        v.x *= alpha; v.y *= alpha; v.z *= alpha; v.w *= alpha;
        if (!TRANS && bias) {
            v.x += bias[n0 + c4];
            v.y += bias[n0 + c4 + 1];
            v.z += bias[n0 + c4 + 2];
            v.w += bias[n0 + c4 + 3];
        }
        size_t o = (size_t)z * sC + (size_t)(OB + row) * ldc + IB + c4;
        if (Cf) *reinterpret_cast<float4*>(Cf + o) = v;
        if (Ch) {
            if (Cl) {
                h16 h0, l0, h1, l1, h2, l2, h3, l3;
                split2h(v.x, h0, l0); split2h(v.y, h1, l1);
                split2h(v.z, h2, l2); split2h(v.w, h3, l3);
                *reinterpret_cast<uint2*>(Ch + o) = make_uint2(pack2(h0, h1), pack2(h2, h3));
                *reinterpret_cast<uint2*>(Cl + o) = make_uint2(pack2(l0, l1), pack2(l2, l3));
            } else {
                *reinterpret_cast<uint2*>(Ch + o) =
                    make_uint2(pack2(__float2half_rn(v.x), __float2half_rn(v.y)),
                               pack2(__float2half_rn(v.z), __float2half_rn(v.w)));
            }
        }
    }
}

// ---------------- host-side launcher ----------------
static void launch_gemm(bool trans, bool twob,
                        const h16* A, size_t sA,
                        const h16* Bh, const h16* Bl, size_t sB,
                        float* Cf, h16* Ch, h16* Cl, size_t sC,
                        int M, int N, int K, int ldc, float alpha,
                        const float* bias, int batch) {
    dim3 grid(N / BN, M / BM, batch);
    if (trans)
        gemm_mma<true, true><<<grid, NTHR, SMEM_TWOB>>>(A, sA, Bh, Bl, sB, Cf, Ch, Cl, sC,
                                                        M, N, K, ldc, alpha, bias);
    else if (twob)
        gemm_mma<false, true><<<grid, NTHR, SMEM_TWOB>>>(A, sA, Bh, Bl, sB, Cf, Ch, Cl, sC,
                                                         M, N, K, ldc, alpha, bias);
    else
        gemm_mma<false, false><<<grid, NTHR, SMEM_ONEB>>>(A, sA, Bh, nullptr, sB, Cf, Ch, Cl, sC,
                                                          M, N, K, ldc, alpha, bias);
}

#define SYM(var, sym)                                   \
    do {                                                \
        void* _p = nullptr;                             \
        cudaGetSymbolAddress(&_p, sym);                 \
        var = (decltype(var))_p;                        \
    } while (0)

extern "C" void kernel_launch(void* const* d_in, const int* in_sizes, int n_in,
                              void* d_out, int out_size) {
    const int*   input_text = (const int*)d_in[0];
    const float* target     = (const float*)d_in[1];
    const float* embed      = (const float*)d_in[2];
    const float* in_proj_w  = (const float*)d_in[3];
    const float* out_w      = (const float*)d_in[4];
    const float* out_b      = (const float*)d_in[5];
    const float* lin_w      = (const float*)d_in[6];
    const float* lin_b      = (const float*)d_in[7];
    float*       logits     = (float*)d_out;

    cudaFuncSetAttribute(gemm_mma<false, true>,
                         cudaFuncAttributeMaxDynamicSharedMemorySize, SMEM_TWOB);
    cudaFuncSetAttribute(gemm_mma<false, false>,
                         cudaFuncAttributeMaxDynamicSharedMemorySize, SMEM_ONEB);
    cudaFuncSetAttribute(gemm_mma<true, true>,
                         cudaFuncAttributeMaxDynamicSharedMemorySize, SMEM_TWOB);

    h16 *x, *T, *q, *p, *o, *k, *vT, *lin;
    h16 *w_h, *w_l, *wo_h, *wo_l;
    float* sc;
    SYM(x, g_x);   SYM(T, g_T);   SYM(q, g_q);   SYM(p, g_p);   SYM(o, g_o);
    SYM(k, g_k);   SYM(vT, g_vT); SYM(lin, g_lin);
    SYM(w_h, g_w_h);   SYM(w_l, g_w_l);
    SYM(wo_h, g_wo_h); SYM(wo_l, g_wo_l);
    SYM(sc, g_scores);

    gather_h<<<MTOT, 256>>>(input_text, embed, x);              // launch 1
    conv_h<<<4096, 256>>>(target, T, (size_t)MTOT * EDIM / 4);  // launch 2

    const size_t EE = (size_t)EDIM * EDIM;

    for (int l = 0; l < NL; l++) {
        split_h<<<3072, 256>>>(in_proj_w + (size_t)l * 3 * EE, w_h, w_l, 3 * EE / 4);  // 3

        // q = (x @ Wq^T) * SCALE      (hi only out)   <- 4th launch: profiled GEMM
        launch_gemm(false, true, x, 0, w_h, w_l, 0,
                    nullptr, q, nullptr, 0,
                    MTOT, EDIM, EDIM, EDIM, SCALE_Q, nullptr, 1);

        split_h<<<1024, 256>>>(out_w + (size_t)l * EE, wo_h, wo_l, EE / 4);

        // k = target @ Wk^T           (hi only out)
        launch_gemm(false, true, T, 0, w_h + EE, w_l + EE, 0,
                    nullptr, k, nullptr, 0,
                    MTOT, EDIM, EDIM, EDIM, 1.f, nullptr, 1);
        // vT[b] = (target_b @ Wv^T)^T (hi only out, transposed store)
        launch_gemm(true, true, T, (size_t)SKV * EDIM, w_h + 2 * EE, w_l + 2 * EE, 0,
                    nullptr, vT, nullptr, (size_t)EDIM * SKV,
                    SKV, EDIM, EDIM, SKV, 1.f, nullptr, NB);
        // scores[b] = q_b @ k_b^T     (fp32 out, single-term B)
        launch_gemm(false, false, q, (size_t)SQ * EDIM, k, nullptr, (size_t)SKV * EDIM,
                    sc, nullptr, nullptr, (size_t)SQ * SKV,
                    SQ, SKV, EDIM, SKV, 1.f, nullptr, NB);
        softmax_h<<<NB * SQ, 256>>>(sc, p);
        // o[b] = attn_b @ vT_b^T      (hi only out, single-term B)
        launch_gemm(false, false, p, (size_t)SQ * SKV, vT, nullptr, (size_t)EDIM * SKV,
                    nullptr, o, nullptr, (size_t)SQ * EDIM,
                    SQ, EDIM, SKV, EDIM, 1.f, nullptr, NB);
        // x = o @ out_w^T + out_b     (hi only out)
        launch_gemm(false, true, o, 0, wo_h, wo_l, 0,
                    nullptr, x, nullptr, 0,
                    MTOT, EDIM, EDIM, EDIM, 1.f, out_b + (size_t)l * EDIM, 1);
    }

    // logits = x @ lin_w^T + lin_b    (fp32 out, single-term B)
    conv_h<<<8192, 256>>>(lin_w, lin, (size_t)VOC * EDIM / 4);
    launch_gemm(false, false, x, 0, lin, nullptr, 0,
                logits, nullptr, nullptr, 0,
                MTOT, VOC, EDIM, VOC, 1.f, lin_b, 1);
}

// round 12
// speedup vs baseline: 2.0598x; 1.2219x over previous
#include <cuda_runtime.h>
#include <cuda_fp16.h>
#include <cstdint>

typedef __half h16;

// ---------------- problem constants ----------------
#define NB    8
#define SQ    1024
#define SKV   1024
#define EDIM  1024
#define VOC   32000
#define NL    6
#define MTOT  (NB * SQ)        // 8192
#define SCALE_Q 0.125f

// ---------------- device scratch ----------------
__device__ __align__(16) h16  g_x  [MTOT * EDIM];
__device__ __align__(16) h16  g_T  [MTOT * EDIM];
__device__ __align__(16) h16  g_q  [MTOT * EDIM];
__device__ __align__(16) h16  g_p  [NB * SQ * SKV];
__device__ __align__(16) h16  g_o  [MTOT * EDIM];
__device__ __align__(16) h16  g_k  [MTOT * EDIM];
__device__ __align__(16) h16  g_vT [MTOT * EDIM];
__device__ __align__(16) h16  g_lin[VOC * EDIM];
__device__ __align__(16) h16  g_w  [3 * EDIM * EDIM];
__device__ __align__(16) h16  g_wo [EDIM * EDIM];
__device__ float g_scores[NB * SQ * SKV];

// ---------------- helpers ----------------
__device__ __forceinline__ uint32_t pack2(h16 a, h16 b) {
    __half2 p = __halves2half2(a, b);
    return *reinterpret_cast<uint32_t*>(&p);
}

// fp32 -> fp16, vectorized (n4 = count of float4)
__global__ void conv_h(const float* __restrict__ src, h16* __restrict__ h, size_t n4) {
    size_t stride = (size_t)gridDim.x * blockDim.x;
    for (size_t i = (size_t)blockIdx.x * blockDim.x + threadIdx.x; i < n4; i += stride) {
        float4 v = reinterpret_cast<const float4*>(src)[i];
        reinterpret_cast<uint2*>(h)[i] =
            make_uint2(pack2(__float2half_rn(v.x), __float2half_rn(v.y)),
                       pack2(__float2half_rn(v.z), __float2half_rn(v.w)));
    }
}

// embedding gather -> fp16; one block (256 thr) per row, 4 cols/thread
__global__ void gather_h(const int* __restrict__ idx, const float* __restrict__ embed,
                         h16* __restrict__ x) {
    int row = blockIdx.x;
    int tok = idx[row];
    const float4* src = reinterpret_cast<const float4*>(embed + (size_t)tok * EDIM);
    float4 v = src[threadIdx.x];
    reinterpret_cast<uint2*>(x + (size_t)row * EDIM)[threadIdx.x] =
        make_uint2(pack2(__float2half_rn(v.x), __float2half_rn(v.y)),
                   pack2(__float2half_rn(v.z), __float2half_rn(v.w)));
}

// row softmax over 1024 cols -> fp16; 256 threads/row
__global__ void softmax_h(const float* __restrict__ S, h16* __restrict__ P) {
    int row = blockIdx.x;
    int t = threadIdx.x;
    int lane = t & 31, w = t >> 5;
    float4 v = reinterpret_cast<const float4*>(S + (size_t)row * SKV)[t];

    float m = fmaxf(fmaxf(v.x, v.y), fmaxf(v.z, v.w));
#pragma unroll
    for (int off = 16; off > 0; off >>= 1)
        m = fmaxf(m, __shfl_xor_sync(0xFFFFFFFFu, m, off));
    __shared__ float red[8];
    if (lane == 0) red[w] = m;
    __syncthreads();
    float mx = red[0];
#pragma unroll
    for (int i = 1; i < 8; i++) mx = fmaxf(mx, red[i]);

    v.x = __expf(v.x - mx); v.y = __expf(v.y - mx);
    v.z = __expf(v.z - mx); v.w = __expf(v.w - mx);
    float s = v.x + v.y + v.z + v.w;
#pragma unroll
    for (int off = 16; off > 0; off >>= 1)
        s += __shfl_xor_sync(0xFFFFFFFFu, s, off);
    __shared__ float red2[8];
    if (lane == 0) red2[w] = s;
    __syncthreads();
    float tot = red2[0];
#pragma unroll
    for (int i = 1; i < 8; i++) tot += red2[i];
    float inv = 1.f / tot;

    reinterpret_cast<uint2*>(P + (size_t)row * SKV)[t] =
        make_uint2(pack2(__float2half_rn(v.x * inv), __float2half_rn(v.y * inv)),
                   pack2(__float2half_rn(v.z * inv), __float2half_rn(v.w * inv)));
}

// ---------------- mma.sync fp16 GEMM, 128x128x32 tile, 256 threads, 2 CTAs/SM ----------------
// C[m,n] = alpha * sum_k A[m,k]*B[n,k] + bias[n]; single-term fp16, fp32 acc.
// 8 warps as 2(m) x 4(n); warp tile 64x32; 5-stage cp.async.

#define BK        32
#define BM        128
#define BN        128
#define NTHR      256
#define LDROW     80
#define A_BYTES   (BM * LDROW)                // 10240
#define B_BYTES   (BN * LDROW)                // 10240
#define NSTAGE    5
#define STAGE_B   (A_BYTES + B_BYTES)         // 20480
#define GSMEM     (NSTAGE * STAGE_B)          // 102400 (>= epilogue 128*132*4 = 67584)
#define GROUP_Y   8

__device__ __forceinline__ uint32_t smem_u32(const void* p) {
    uint32_t a;
    asm("{ .reg .u64 t; cvta.to.shared.u64 t, %1; cvt.u32.u64 %0, t; }" : "=r"(a) : "l"(p));
    return a;
}

__device__ __forceinline__ void ldm_x4(uint32_t& r0, uint32_t& r1, uint32_t& r2,
                                       uint32_t& r3, uint32_t addr) {
    asm volatile("ldmatrix.sync.aligned.m8n8.x4.shared.b16 {%0,%1,%2,%3}, [%4];"
                 : "=r"(r0), "=r"(r1), "=r"(r2), "=r"(r3) : "r"(addr));
}

__device__ __forceinline__ void mma16816(float* c, const uint32_t* a, const uint32_t* b) {
    asm volatile(
        "mma.sync.aligned.m16n8k16.row.col.f32.f16.f16.f32 "
        "{%0,%1,%2,%3}, {%4,%5,%6,%7}, {%8,%9}, {%0,%1,%2,%3};"
        : "+f"(c[0]), "+f"(c[1]), "+f"(c[2]), "+f"(c[3])
        : "r"(a[0]), "r"(a[1]), "r"(a[2]), "r"(a[3]), "r"(b[0]), "r"(b[1]));
}

__device__ __forceinline__ void fill_stage(uint32_t sbase,
    const h16* __restrict__ A0, const h16* __restrict__ B0,
    int K, int k0, int tid)
{
    // A: 128 rows x 4 chunks of 16B = 512 tasks, 256 threads -> 2 rounds
#pragma unroll
    for (int j = 0; j < 2; j++) {
        int e = tid + j * NTHR;
        int row = e >> 2, c = e & 3;
        uint32_t dst = sbase + row * LDROW + c * 16;
        uint64_t src = __cvta_generic_to_global((const void*)(A0 + (size_t)row * K + k0 + c * 8));
        asm volatile("cp.async.cg.shared.global [%0], [%1], 16;" :: "r"(dst), "l"(src));
    }
    // B: 128 rows x 4 chunks = 512 tasks -> 2 rounds
#pragma unroll
    for (int j = 0; j < 2; j++) {
        int e = tid + j * NTHR;
        int row = e >> 2, c = e & 3;
        uint32_t dst = sbase + A_BYTES + row * LDROW + c * 16;
        uint64_t src = __cvta_generic_to_global((const void*)(B0 + (size_t)row * K + k0 + c * 8));
        asm volatile("cp.async.cg.shared.global [%0], [%1], 16;" :: "r"(dst), "l"(src));
    }
    asm volatile("cp.async.commit_group;" ::: "memory");
}

template <bool TRANS>
__global__ void __launch_bounds__(NTHR, 2)
gemm_mma(const h16* __restrict__ A, size_t sA,
         const h16* __restrict__ Bh, size_t sB,
         float* __restrict__ Cf, h16* __restrict__ Ch, size_t sC,
         int M, int N, int K, int ldc, float alpha, const float* __restrict__ bias)
{
    extern __shared__ __align__(128) char smem[];
    const uint32_t sb = smem_u32(smem);
    const int tid  = threadIdx.x;
    const int wid  = tid >> 5;
    const int lane = tid & 31;
    const int wm = wid >> 2;                  // 0..1 : 64-row block
    const int wn = wid & 3;                   // 0..3 : 32-col block
    const int z  = blockIdx.z;

    // grouped rasterization
    int lin = blockIdx.y * gridDim.x + blockIdx.x;
    int gsz = GROUP_Y * gridDim.x;
    int grp = lin / gsz, rem = lin % gsz;
    int span = min(GROUP_Y, (int)gridDim.y - grp * GROUP_Y);
    int by = grp * GROUP_Y + rem % span;
    int bx = rem / span;
    const int m0 = by * BM;
    const int n0 = bx * BN;

    const h16* A0 = A  + (size_t)z * sA + (size_t)m0 * K;
    const h16* B0 = Bh + (size_t)z * sB + (size_t)n0 * K;

    const uint32_t a_base = (uint32_t)((wm * 64 + (lane & 15)) * LDROW + (lane >> 4) * 16);
    const uint32_t b_base = (uint32_t)((wn * 32 + (lane >> 4) * 8 + (lane & 7)) * LDROW
                                       + ((lane >> 3) & 1) * 16);

    float acc[4][4][4];
#pragma unroll
    for (int i = 0; i < 4; i++)
#pragma unroll
        for (int j = 0; j < 4; j++)
#pragma unroll
            for (int r = 0; r < 4; r++) acc[i][j][r] = 0.f;

    const int KT = K / BK;

#pragma unroll
    for (int s = 0; s < NSTAGE - 1; s++)
        fill_stage(sb + s * STAGE_B, A0, B0, K, s * BK, tid);

    int stage = 0;
    for (int kt = 0; kt < KT; kt++) {
        asm volatile("cp.async.wait_group %0;" :: "n"(NSTAGE - 2) : "memory");
        __syncthreads();

        int f = kt + NSTAGE - 1;
        if (f < KT)
            fill_stage(sb + (f % NSTAGE) * STAGE_B, A0, B0, K, f * BK, tid);
        else
            asm volatile("cp.async.commit_group;" ::: "memory");  // keep group-count semantics

        const uint32_t sA_ = sb + stage * STAGE_B;
        const uint32_t sB_ = sA_ + A_BYTES;

#pragma unroll
        for (int ks = 0; ks < 2; ks++) {
            const uint32_t ko = ks * 32;
            uint32_t ah[4][4], bh[4][2];
#pragma unroll
            for (int mi = 0; mi < 4; mi++) {
                uint32_t off = a_base + mi * 16 * LDROW + ko;
                ldm_x4(ah[mi][0], ah[mi][1], ah[mi][2], ah[mi][3], sA_ + off);
            }
#pragma unroll
            for (int p = 0; p < 2; p++) {
                uint32_t off = b_base + p * 16 * LDROW + ko;
                ldm_x4(bh[2 * p][0], bh[2 * p][1], bh[2 * p + 1][0], bh[2 * p + 1][1], sB_ + off);
            }
#pragma unroll
            for (int mi = 0; mi < 4; mi++)
#pragma unroll
                for (int ni = 0; ni < 4; ni++)
                    mma16816(acc[mi][ni], ah[mi], bh[ni]);
        }
        stage = (stage + 1 == NSTAGE) ? 0 : stage + 1;
    }

    asm volatile("cp.async.wait_group 0;" ::: "memory");
    __syncthreads();

    // ---------------- epilogue (128x128, LD=132 both orientations) ----------------
    const int LD = 132;
    float* SE = reinterpret_cast<float*>(smem);
    const int tr = lane >> 2;
    const int tc = (lane & 3) * 2;
#pragma unroll
    for (int mi = 0; mi < 4; mi++)
#pragma unroll
        for (int ni = 0; ni < 4; ni++) {
            int r0 = wm * 64 + mi * 16 + tr;
            int c0 = wn * 32 + ni * 8 + tc;
            if (!TRANS) {
                SE[r0 * LD + c0]           = acc[mi][ni][0];
                SE[r0 * LD + c0 + 1]       = acc[mi][ni][1];
                SE[(r0 + 8) * LD + c0]     = acc[mi][ni][2];
                SE[(r0 + 8) * LD + c0 + 1] = acc[mi][ni][3];
            } else {
                SE[c0 * LD + r0]           = acc[mi][ni][0];
                SE[(c0 + 1) * LD + r0]     = acc[mi][ni][1];
                SE[c0 * LD + r0 + 8]       = acc[mi][ni][2];
                SE[(c0 + 1) * LD + r0 + 8] = acc[mi][ni][3];
            }
        }
    __syncthreads();

    const int OB = TRANS ? n0 : m0;
    const int IB = TRANS ? m0 : n0;
#pragma unroll
    for (int i = 0; i < 16; i++) {
        int e = tid + i * NTHR;               // 0..4095 float4s
        int row = e >> 5;
        int c4 = (e & 31) * 4;
        float4 v = *reinterpret_cast<float4*>(&SE[row * LD + c4]);
        v.x *= alpha; v.y *= alpha; v.z *= alpha; v.w *= alpha;
        if (!TRANS && bias) {
            v.x += bias[n0 + c4];
            v.y += bias[n0 + c4 + 1];
            v.z += bias[n0 + c4 + 2];
            v.w += bias[n0 + c4 + 3];
        }
        size_t o = (size_t)z * sC + (size_t)(OB + row) * ldc + IB + c4;
        if (Cf) *reinterpret_cast<float4*>(Cf + o) = v;
        if (Ch) {
            *reinterpret_cast<uint2*>(Ch + o) =
                make_uint2(pack2(__float2half_rn(v.x), __float2half_rn(v.y)),
                           pack2(__float2half_rn(v.z), __float2half_rn(v.w)));
        }
    }
}

// ---------------- host-side launcher ----------------
static void launch_gemm(bool trans,
                        const h16* A, size_t sA,
                        const h16* B, size_t sB,
                        float* Cf, h16* Ch, size_t sC,
                        int M, int N, int K, int ldc, float alpha,
                        const float* bias, int batch) {
    dim3 grid(N / BN, M / BM, batch);
    if (trans)
        gemm_mma<true><<<grid, NTHR, GSMEM>>>(A, sA, B, sB, Cf, Ch, sC,
                                              M, N, K, ldc, alpha, bias);
    else
        gemm_mma<false><<<grid, NTHR, GSMEM>>>(A, sA, B, sB, Cf, Ch, sC,
                                               M, N, K, ldc, alpha, bias);
}

#define SYM(var, sym)                                   \
    do {                                                \
        void* _p = nullptr;                             \
        cudaGetSymbolAddress(&_p, sym);                 \
        var = (decltype(var))_p;                        \
    } while (0)

extern "C" void kernel_launch(void* const* d_in, const int* in_sizes, int n_in,
                              void* d_out, int out_size) {
    const int*   input_text = (const int*)d_in[0];
    const float* target     = (const float*)d_in[1];
    const float* embed      = (const float*)d_in[2];
    const float* in_proj_w  = (const float*)d_in[3];
    const float* out_w      = (const float*)d_in[4];
    const float* out_b      = (const float*)d_in[5];
    const float* lin_w      = (const float*)d_in[6];
    const float* lin_b      = (const float*)d_in[7];
    float*       logits     = (float*)d_out;

    cudaFuncSetAttribute(gemm_mma<false>,
                         cudaFuncAttributeMaxDynamicSharedMemorySize, GSMEM);
    cudaFuncSetAttribute(gemm_mma<true>,
                         cudaFuncAttributeMaxDynamicSharedMemorySize, GSMEM);

    h16 *x, *T, *q, *p, *o, *k, *vT, *lin, *w, *wo;
    float* sc;
    SYM(x, g_x);   SYM(T, g_T);   SYM(q, g_q);   SYM(p, g_p);   SYM(o, g_o);
    SYM(k, g_k);   SYM(vT, g_vT); SYM(lin, g_lin);
    SYM(w, g_w);   SYM(wo, g_wo);
    SYM(sc, g_scores);

    gather_h<<<MTOT, 256>>>(input_text, embed, x);              // launch 1
    conv_h<<<4096, 256>>>(target, T, (size_t)MTOT * EDIM / 4);  // launch 2

    const size_t EE = (size_t)EDIM * EDIM;

    for (int l = 0; l < NL; l++) {
        conv_h<<<3072, 256>>>(in_proj_w + (size_t)l * 3 * EE, w, 3 * EE / 4);  // 3

        // q = (x @ Wq^T) * SCALE      <- 4th launch: profiled GEMM
        launch_gemm(false, x, 0, w, 0,
                    nullptr, q, 0,
                    MTOT, EDIM, EDIM, EDIM, SCALE_Q, nullptr, 1);

        conv_h<<<1024, 256>>>(out_w + (size_t)l * EE, wo, EE / 4);

        // k = target @ Wk^T
        launch_gemm(false, T, 0, w + EE, 0,
                    nullptr, k, 0,
                    MTOT, EDIM, EDIM, EDIM, 1.f, nullptr, 1);
        // vT[b] = (target_b @ Wv^T)^T  (transposed store)
        launch_gemm(true, T, (size_t)SKV * EDIM, w + 2 * EE, 0,
                    nullptr, vT, (size_t)EDIM * SKV,
                    SKV, EDIM, EDIM, SKV, 1.f, nullptr, NB);
        // scores[b] = q_b @ k_b^T      (fp32 out)
        launch_gemm(false, q, (size_t)SQ * EDIM, k, (size_t)SKV * EDIM,
                    sc, nullptr, (size_t)SQ * SKV,
                    SQ, SKV, EDIM, SKV, 1.f, nullptr, NB);
        softmax_h<<<NB * SQ, 256>>>(sc, p);
        // o[b] = attn_b @ vT_b^T
        launch_gemm(false, p, (size_t)SQ * SKV, vT, (size_t)EDIM * SKV,
                    nullptr, o, (size_t)SQ * EDIM,
                    SQ, EDIM, SKV, EDIM, 1.f, nullptr, NB);
        // x = o @ out_w^T + out_b
        launch_gemm(false, o, 0, wo, 0,
                    nullptr, x, 0,
                    MTOT, EDIM, EDIM, EDIM, 1.f, out_b + (size_t)l * EDIM, 1);
    }

    // logits = x @ lin_w^T + lin_b     (fp32 out)
    conv_h<<<8192, 256>>>(lin_w, lin, (size_t)VOC * EDIM / 4);
    launch_gemm(false, x, 0, lin, 0,
                logits, nullptr, 0,
                MTOT, VOC, EDIM, VOC, 1.f, lin_b, 1);
}